// round 5
// baseline (speedup 1.0000x reference)
#include <cuda_runtime.h>
#include <math.h>
#include <stdint.h>

#define BATCH   65536
#define IN_DIM  512
#define LATENT  32
#define NTRI    528
#define NPAD    544
#define WENC_PAD 524

#define MU_OFF  ((size_t)BATCH*LATENT)
#define COV_OFF ((size_t)BATCH*LATENT*2)

typedef unsigned long long ull;

__device__ __forceinline__ float lrelu(float v) { return v >= 0.f ? v : 0.01f * v; }
__device__ __forceinline__ ull pk2(float lo, float hi) {
    ull r; asm("mov.b64 %0, {%1,%2};" : "=l"(r) : "f"(lo), "f"(hi)); return r;
}
__device__ __forceinline__ float lo2(ull v) {
    float f; asm("{ .reg .f32 h; mov.b64 {%0, h}, %1; }" : "=f"(f) : "l"(v)); return f;
}
__device__ __forceinline__ float hi2(ull v) {
    float f; asm("{ .reg .f32 l; mov.b64 {l, %0}, %1; }" : "=f"(f) : "l"(v)); return f;
}
__device__ __forceinline__ ull fma2(ull a, ull b, ull c) {
    ull d; asm("fma.rn.f32x2 %0, %1, %2, %3;" : "=l"(d) : "l"(a), "l"(b), "l"(c)); return d;
}
#define ROWOFF64(i) ((i)*((i)+1)/2 + (((i)+1)>>1))

// ============================ Kernel 1: encoder ============================
#define K1_THREADS 512
#define K1_RPW 8
#define K1_TILE 128                      // 16 warps * 8 rows
#define K1_NTILES (BATCH / K1_TILE)      // 512
#define K1_GRID 304
#define K1_SMEM_FLOATS (LATENT*WENC_PAD + 32)   // 16800 floats = 67200 B

__global__ void __launch_bounds__(K1_THREADS, 2)
enc_kernel(const float* __restrict__ x,       const float* __restrict__ W_enc,
           const float* __restrict__ b_enc,   const float* __restrict__ bn_gamma,
           const float* __restrict__ bn_beta, const float* __restrict__ bn_mean,
           const float* __restrict__ bn_var,  float* __restrict__ out)
{
    extern __shared__ float sm[];
    __shared__ float s_scale[32];
    const int tid = threadIdx.x;

    if (tid < 32) {
        float s = bn_gamma[tid] * rsqrtf(bn_var[tid] + 1e-5f);
        s_scale[tid] = s;
        sm[LATENT*WENC_PAD + tid] = (b_enc[tid] - bn_mean[tid]) * s + bn_beta[tid];
    }
    __syncthreads();
    for (int idx = tid; idx < IN_DIM * LATENT; idx += K1_THREADS) {
        int k = idx >> 5, j = idx & 31;
        sm[j * WENC_PAD + k] = W_enc[idx] * s_scale[j];   // transposed + BN fold
    }
    __syncthreads();

    const int warp = tid >> 5, lane = tid & 31;
    const float* wrow = sm + lane * WENC_PAD;
    const float bj = sm[LATENT*WENC_PAD + lane];

    for (int tile = blockIdx.x; tile < K1_NTILES; tile += gridDim.x) {
        const int rbase = tile * K1_TILE + warp * K1_RPW;
        const float4* xr = (const float4*)(x + (size_t)rbase * IN_DIM);

        ull a0 = 0ull, a1 = 0ull, a2 = 0ull, a3 = 0ull;
        #pragma unroll 4
        for (int kc = 0; kc < IN_DIM / 4; kc++) {
            float4 wv = *(const float4*)(wrow + kc * 4);
            ull wdx = pk2(wv.x, wv.x), wdy = pk2(wv.y, wv.y);
            ull wdz = pk2(wv.z, wv.z), wdw = pk2(wv.w, wv.w);
            // row pair 0 (rows 0,1)
            {
                float4 v0 = xr[0 * (IN_DIM/4) + kc];   // uniform-address broadcast
                float4 v1 = xr[1 * (IN_DIM/4) + kc];
                a0 = fma2(pk2(v0.x, v1.x), wdx, a0);
                a0 = fma2(pk2(v0.y, v1.y), wdy, a0);
                a0 = fma2(pk2(v0.z, v1.z), wdz, a0);
                a0 = fma2(pk2(v0.w, v1.w), wdw, a0);
            }
            {
                float4 v0 = xr[2 * (IN_DIM/4) + kc];
                float4 v1 = xr[3 * (IN_DIM/4) + kc];
                a1 = fma2(pk2(v0.x, v1.x), wdx, a1);
                a1 = fma2(pk2(v0.y, v1.y), wdy, a1);
                a1 = fma2(pk2(v0.z, v1.z), wdz, a1);
                a1 = fma2(pk2(v0.w, v1.w), wdw, a1);
            }
            {
                float4 v0 = xr[4 * (IN_DIM/4) + kc];
                float4 v1 = xr[5 * (IN_DIM/4) + kc];
                a2 = fma2(pk2(v0.x, v1.x), wdx, a2);
                a2 = fma2(pk2(v0.y, v1.y), wdy, a2);
                a2 = fma2(pk2(v0.z, v1.z), wdz, a2);
                a2 = fma2(pk2(v0.w, v1.w), wdw, a2);
            }
            {
                float4 v0 = xr[6 * (IN_DIM/4) + kc];
                float4 v1 = xr[7 * (IN_DIM/4) + kc];
                a3 = fma2(pk2(v0.x, v1.x), wdx, a3);
                a3 = fma2(pk2(v0.y, v1.y), wdy, a3);
                a3 = fma2(pk2(v0.z, v1.z), wdz, a3);
                a3 = fma2(pk2(v0.w, v1.w), wdw, a3);
            }
        }
        out[(size_t)(rbase + 0) * 32 + lane] = lrelu(lo2(a0) + bj);
        out[(size_t)(rbase + 1) * 32 + lane] = lrelu(hi2(a0) + bj);
        out[(size_t)(rbase + 2) * 32 + lane] = lrelu(lo2(a1) + bj);
        out[(size_t)(rbase + 3) * 32 + lane] = lrelu(hi2(a1) + bj);
        out[(size_t)(rbase + 4) * 32 + lane] = lrelu(lo2(a2) + bj);
        out[(size_t)(rbase + 5) * 32 + lane] = lrelu(hi2(a2) + bj);
        out[(size_t)(rbase + 6) * 32 + lane] = lrelu(lo2(a3) + bj);
        out[(size_t)(rbase + 7) * 32 + lane] = lrelu(hi2(a3) + bj);
    }
}

// ======================= Kernel 2: mu / ch / cov ===========================
#define K2_THREADS 384
#define K2_WARPS   12
#define K2_RPW     4
#define K2_TILE    (K2_WARPS * K2_RPW)          // 48
#define K2_NTILES  ((BATCH + K2_TILE - 1) / K2_TILE)   // 1366 (last partial)
#define K2_GRID    152

// smem layout (floats)
#define OFF2_WCH  0
#define OFF2_WMU  (OFF2_WCH + LATENT*NPAD)      // 17408
#define OFF2_BMU  (OFF2_WMU + LATENT*LATENT)    // 18432
#define OFF2_BCH  (OFF2_BMU + 32)               // 18464
#define OFF2_LBUF (OFF2_BCH + NPAD)             // 19008 (16B aligned)
#define K2_LBUF_FLOATS (2 * 544 * 2)            // 2176 floats (= 1088 u64) per warp
#define K2_SMEM_FLOATS (OFF2_LBUF + K2_WARPS * K2_LBUF_FLOATS)  // 45120 floats = 180480 B
#define LPAIR_U64 544

__global__ void __launch_bounds__(K2_THREADS)
tail_kernel(const float* __restrict__ W_mu, const float* __restrict__ b_mu,
            const float* __restrict__ W_ch, const float* __restrict__ b_ch,
            float* out)
{
    extern __shared__ float sm[];
    const int tid = threadIdx.x;

    // ---- stage weights ----
    // W_ch col-pair interleave: word w in row k:
    //   w < 512: cp=w>>6, ln=(w&63)>>1, s=w&1 -> col (2cp+s)*32+ln
    //   w >= 512: col w (512..527 real, rest 0)
    for (int idx = tid; idx < LATENT * NPAD; idx += K2_THREADS) {
        int k = idx / NPAD, w = idx - k * NPAD;
        float v;
        if (w < 512) {
            int cp = w >> 6, ln = (w & 63) >> 1, s = w & 1;
            v = W_ch[k * NTRI + (2 * cp + s) * 32 + ln];
        } else {
            v = (w < NTRI) ? W_ch[k * NTRI + w] : 0.f;
        }
        sm[OFF2_WCH + idx] = v;
    }
    for (int idx = tid; idx < LATENT * LATENT; idx += K2_THREADS) sm[OFF2_WMU + idx] = W_mu[idx];
    if (tid < 32) sm[OFF2_BMU + tid] = b_mu[tid];
    for (int idx = tid; idx < NPAD; idx += K2_THREADS) sm[OFF2_BCH + idx] = (idx < NTRI) ? b_ch[idx] : 0.f;
    __syncthreads();

    const int warp = tid >> 5, lane = tid & 31;
    ull* Lp0 = (ull*)(sm + OFF2_LBUF) + warp * (2 * LPAIR_U64);
    ull* Lp1 = Lp0 + LPAIR_U64;

    for (int tile = blockIdx.x; tile < K2_NTILES; tile += gridDim.x) {
        const int rbase = tile * K2_TILE + warp * K2_RPW;
        if (rbase >= BATCH) continue;          // partial last tile: per-warp guard

        // ---- load h (written by enc_kernel into out[0:BATCH*32)) ----
        float h0 = out[(size_t)(rbase + 0) * 32 + lane];
        float h1 = out[(size_t)(rbase + 1) * 32 + lane];
        float h2 = out[(size_t)(rbase + 2) * 32 + lane];
        float h3 = out[(size_t)(rbase + 3) * 32 + lane];

        // ---- mu + ch GEMMs (f32x2, col-pair weights) ----
        ull acp[K2_RPW][8];
        float ac16[K2_RPW];
        ull amu01 = 0ull, amu23 = 0ull;
        #pragma unroll
        for (int r = 0; r < K2_RPW; r++) {
            ac16[r] = 0.f;
            #pragma unroll
            for (int cp = 0; cp < 8; cp++) acp[r][cp] = 0ull;
        }

        #pragma unroll 2
        for (int k = 0; k < LATENT; k++) {
            float hv0 = __shfl_sync(0xffffffffu, h0, k);
            float hv1 = __shfl_sync(0xffffffffu, h1, k);
            float hv2 = __shfl_sync(0xffffffffu, h2, k);
            float hv3 = __shfl_sync(0xffffffffu, h3, k);
            float wm = sm[OFF2_WMU + k * 32 + lane];
            ull wmd  = pk2(wm, wm);
            amu01 = fma2(pk2(hv0, hv1), wmd, amu01);
            amu23 = fma2(pk2(hv2, hv3), wmd, amu23);
            ull hd0 = pk2(hv0, hv0), hd1 = pk2(hv1, hv1), hd2 = pk2(hv2, hv2), hd3 = pk2(hv3, hv3);
            const ull* w2 = (const ull*)(sm + OFF2_WCH + k * NPAD) + lane;
            #pragma unroll
            for (int cp = 0; cp < 8; cp++) {
                ull w = w2[cp * 32];
                acp[0][cp] = fma2(hd0, w, acp[0][cp]);
                acp[1][cp] = fma2(hd1, w, acp[1][cp]);
                acp[2][cp] = fma2(hd2, w, acp[2][cp]);
                acp[3][cp] = fma2(hd3, w, acp[3][cp]);
            }
            float wc16 = sm[OFF2_WCH + k * NPAD + 512 + lane];
            ac16[0] = fmaf(hv0, wc16, ac16[0]);
            ac16[1] = fmaf(hv1, wc16, ac16[1]);
            ac16[2] = fmaf(hv2, wc16, ac16[2]);
            ac16[3] = fmaf(hv3, wc16, ac16[3]);
        }
        {
            float bm = sm[OFF2_BMU + lane];
            out[MU_OFF + (size_t)(rbase + 0) * 32 + lane] = lrelu(lo2(amu01) + bm);
            out[MU_OFF + (size_t)(rbase + 1) * 32 + lane] = lrelu(hi2(amu01) + bm);
            out[MU_OFF + (size_t)(rbase + 2) * 32 + lane] = lrelu(lo2(amu23) + bm);
            out[MU_OFF + (size_t)(rbase + 3) * 32 + lane] = lrelu(hi2(amu23) + bm);
        }

        // ---- elts -> pair-interleaved padded-tri L (u64 = 2 batch rows) ----
        __syncwarp();
        #pragma unroll
        for (int c = 0; c < 17; c++) {
            int e = c * 32 + lane;
            if (c == 16 && e >= NTRI) continue;
            int i = (int)((sqrtf(8.f * (float)e + 1.f) - 1.f) * 0.5f);
            int t = i * (i + 1) >> 1;
            if (e < t)               { i--; t -= i + 1; }
            else if (e >= t + i + 1) { t += i + 1; i++; }
            int off = (t + ((i + 1) >> 1)) + (e - t);   // ROWOFF64(i) + j
            float bc = sm[OFF2_BCH + e];
            float v0, v1, v2, v3;
            if (c < 16) {
                ull p0 = acp[0][c >> 1], p1 = acp[1][c >> 1], p2 = acp[2][c >> 1], p3 = acp[3][c >> 1];
                if (c & 1) { v0 = hi2(p0); v1 = hi2(p1); v2 = hi2(p2); v3 = hi2(p3); }
                else       { v0 = lo2(p0); v1 = lo2(p1); v2 = lo2(p2); v3 = lo2(p3); }
            } else { v0 = ac16[0]; v1 = ac16[1]; v2 = ac16[2]; v3 = ac16[3]; }
            Lp0[off] = pk2(lrelu(v0 + bc), lrelu(v1 + bc));
            Lp1[off] = pk2(lrelu(v2 + bc), lrelu(v3 + bc));
        }
        if (lane < 16) {                       // zero pad of odd-length rows (even i)
            int i = 2 * lane;
            int off = ROWOFF64(i) + i + 1;
            Lp0[off] = 0ull; Lp1[off] = 0ull;
        }
        __syncwarp();
        {
            int off = ROWOFF64(lane) + lane;   // diag transform
            #pragma unroll
            for (int p = 0; p < 2; p++) {
                ull* Lp = p ? Lp1 : Lp0;
                ull v = Lp[off];
                float d0 = lo2(v), d1 = hi2(v);
                float s0 = (d0 > 20.f) ? d0 : log1pf(expf(d0));
                float s1 = (d1 > 20.f) ? d1 : log1pf(expf(d1));
                s0 = fminf(fmaxf(s0, 0.001f), 100.f) + 0.01f;
                s1 = fminf(fmaxf(s1, 0.001f), 100.f) + 0.01f;
                Lp[off] = pk2(s0, s1);
            }
        }
        __syncwarp();

        // ---- cov = L L^T + 0.01 I ; lane = output column; 2 batch rows/pass ----
        const int klo = ROWOFF64(lane);
        #pragma unroll 1
        for (int p = 0; p < 2; p++) {
            const ull* Lp = p ? Lp1 : Lp0;
            ull Lk2[32];
            #pragma unroll
            for (int j = 0; j < 32; j++) {
                ull v = Lp[klo + j];
                Lk2[j] = (j <= lane) ? v : 0ull;
            }
            float* oc0 = out + COV_OFF + (size_t)(rbase + 2 * p)     * 1024;
            float* oc1 = out + COV_OFF + (size_t)(rbase + 2 * p + 1) * 1024;
            #pragma unroll
            for (int i = 0; i < 32; i++) {
                const int ro = ROWOFF64(i);
                const int E  = (i + 2) & ~1;
                ull a0 = 0ull, a1 = 0ull;
                #pragma unroll
                for (int m = 0; m < E; m += 2) {
                    ulonglong2 lv = *(const ulonglong2*)(Lp + ro + m);
                    a0 = fma2(Lk2[m],     lv.x, a0);
                    a1 = fma2(Lk2[m + 1], lv.y, a1);
                }
                float c0 = lo2(a0) + lo2(a1);
                float c1 = hi2(a0) + hi2(a1);
                if (lane == i) { c0 += 0.01f; c1 += 0.01f; }
                oc0[i * 32 + lane] = c0;
                oc1[i * 32 + lane] = c1;
            }
        }
        __syncwarp();
    }
}

// ============================== launcher ===================================
extern "C" void kernel_launch(void* const* d_in, const int* in_sizes, int n_in,
                              void* d_out, int out_size)
{
    (void)in_sizes; (void)n_in; (void)out_size;
    const float* x        = (const float*)d_in[0];
    const float* W_enc    = (const float*)d_in[1];
    const float* b_enc    = (const float*)d_in[2];
    const float* bn_gamma = (const float*)d_in[3];
    const float* bn_beta  = (const float*)d_in[4];
    const float* bn_mean  = (const float*)d_in[5];
    const float* bn_var   = (const float*)d_in[6];
    const float* W_mu     = (const float*)d_in[7];
    const float* b_mu     = (const float*)d_in[8];
    const float* W_ch     = (const float*)d_in[9];
    const float* b_ch     = (const float*)d_in[10];
    float* out = (float*)d_out;

    cudaFuncSetAttribute(enc_kernel, cudaFuncAttributeMaxDynamicSharedMemorySize,
                         K1_SMEM_FLOATS * (int)sizeof(float));
    cudaFuncSetAttribute(tail_kernel, cudaFuncAttributeMaxDynamicSharedMemorySize,
                         K2_SMEM_FLOATS * (int)sizeof(float));

    enc_kernel<<<K1_GRID, K1_THREADS, K1_SMEM_FLOATS * sizeof(float)>>>(
        x, W_enc, b_enc, bn_gamma, bn_beta, bn_mean, bn_var, out);
    tail_kernel<<<K2_GRID, K2_THREADS, K2_SMEM_FLOATS * sizeof(float)>>>(
        W_mu, b_mu, W_ch, b_ch, out);
}

// round 7
// speedup vs baseline: 1.1231x; 1.1231x over previous
#include <cuda_runtime.h>
#include <math.h>
#include <stdint.h>

#define BATCH   65536
#define IN_DIM  512
#define LATENT  32
#define NTRI    528
#define NPAD    544            // padded x row in smem (floats)
#define WENC_PAD 524           // conflict-free float4 weight rows
#define THREADS 256
#define WARPS   8
#define RPW     4
#define TILE_ROWS (WARPS*RPW)  // 32
#define NTILES  (BATCH/TILE_ROWS) // 2048
#define GRID    152

#define LDW      34             // u64 stride of dense L pair rows (32 x 34 u64 = 8704 B)

// ---- smem layout (floats) ----
#define OFF_WENC 0
#define SZ_WENC  (LATENT*WENC_PAD)              // 16768
#define OFF_WCH  (OFF_WENC + SZ_WENC)           // 16768  (col-pair interleaved, 544/row)
#define SZ_WCH   (LATENT*NPAD)                  // 17408
#define OFF_WMU  (OFF_WCH + SZ_WCH)             // 34176
#define OFF_BENC (OFF_WMU + LATENT*LATENT)      // 35200
#define OFF_BMU  (OFF_BENC + 32)                // 35232
#define OFF_BCH  (OFF_BMU + 32)                 // 35264 (544)
#define OFF_S    (OFF_BCH + NPAD)               // 35808
#define OFF_WBUF (OFF_S + 32)                   // 35840 (16B aligned)
#define WBUF_FLOATS (RPW*NPAD)                  // 2176 floats = 8704 B = 1088 u64 (x tile == L buf)
#define SMEM_FLOATS (OFF_WBUF + WARPS*WBUF_FLOATS) // 53248 floats = 212992 B

#define MU_OFF  ((size_t)BATCH*LATENT)
#define COV_OFF ((size_t)BATCH*LATENT*2)

typedef unsigned long long ull;

__device__ __forceinline__ float lrelu(float v) { return v >= 0.f ? v : 0.01f * v; }
__device__ __forceinline__ ull pk2(float lo, float hi) {
    ull r; asm("mov.b64 %0, {%1,%2};" : "=l"(r) : "f"(lo), "f"(hi)); return r;
}
__device__ __forceinline__ float lo2(ull v) {
    float f; asm("{ .reg .f32 h; mov.b64 {%0, h}, %1; }" : "=f"(f) : "l"(v)); return f;
}
__device__ __forceinline__ float hi2(ull v) {
    float f; asm("{ .reg .f32 l; mov.b64 {l, %0}, %1; }" : "=f"(f) : "l"(v)); return f;
}
__device__ __forceinline__ ull fma2(ull a, ull b, ull c) {
    ull d; asm("fma.rn.f32x2 %0, %1, %2, %3;" : "=l"(d) : "l"(a), "l"(b), "l"(c)); return d;
}

__global__ void __launch_bounds__(THREADS)
pm_kernel(const float* __restrict__ x,       const float* __restrict__ W_enc,
          const float* __restrict__ b_enc,   const float* __restrict__ bn_gamma,
          const float* __restrict__ bn_beta, const float* __restrict__ bn_mean,
          const float* __restrict__ bn_var,  const float* __restrict__ W_mu,
          const float* __restrict__ b_mu,    const float* __restrict__ W_ch,
          const float* __restrict__ b_ch,    float* __restrict__ out)
{
    extern __shared__ float sm[];
    const int tid = threadIdx.x;

    // ---- stage + fold weights into smem ----
    if (tid < 32) {
        float s = bn_gamma[tid] * rsqrtf(bn_var[tid] + 1e-5f);
        sm[OFF_S + tid]    = s;
        sm[OFF_BENC + tid] = (b_enc[tid] - bn_mean[tid]) * s + bn_beta[tid];
        sm[OFF_BMU + tid]  = b_mu[tid];
    }
    __syncthreads();
    for (int idx = tid; idx < IN_DIM * LATENT; idx += THREADS) {
        int k = idx >> 5, j = idx & 31;
        sm[OFF_WENC + j * WENC_PAD + k] = W_enc[idx] * sm[OFF_S + j];  // transposed + BN fold
    }
    // W_ch col-pair interleave: word w in row k:
    //   w < 512: cp=w>>6, ln=(w&63)>>1, s=w&1 -> col (2cp+s)*32+ln ;  w >= 512: col w (512..527, rest 0)
    for (int idx = tid; idx < LATENT * NPAD; idx += THREADS) {
        int k = idx / NPAD, w = idx - k * NPAD;
        float v;
        if (w < 512) {
            int cp = w >> 6, ln = (w & 63) >> 1, s = w & 1;
            v = W_ch[k * NTRI + (2 * cp + s) * 32 + ln];
        } else {
            v = (w < NTRI) ? W_ch[k * NTRI + w] : 0.f;
        }
        sm[OFF_WCH + idx] = v;
    }
    for (int idx = tid; idx < LATENT * LATENT; idx += THREADS) sm[OFF_WMU + idx] = W_mu[idx];
    for (int idx = tid; idx < NPAD; idx += THREADS) sm[OFF_BCH + idx] = (idx < NTRI) ? b_ch[idx] : 0.f;
    __syncthreads();

    const int warp = tid >> 5, lane = tid & 31;
    float* xw = sm + OFF_WBUF + warp * WBUF_FLOATS;   // x tile / dense L pair-buf (same 8704B)
    const float* wrow = sm + OFF_WENC + lane * WENC_PAD;
    const float bj = sm[OFF_BENC + lane];
    const float bm = sm[OFF_BMU + lane];

    for (int tile = blockIdx.x; tile < NTILES; tile += gridDim.x) {
        const int rbase = tile * TILE_ROWS + warp * RPW;

        // ---- load x[4][512] into per-warp smem (coalesced float4) ----
        #pragma unroll
        for (int r = 0; r < RPW; r++) {
            const float4* xg = (const float4*)(x + (size_t)(rbase + r) * IN_DIM);
            #pragma unroll
            for (int c = 0; c < 4; c++) {
                float4 v = xg[c * 32 + lane];
                *(float4*)(xw + r * NPAD + c * 128 + lane * 4) = v;
            }
        }
        __syncwarp();

        // ---- enc GEMM: h[r] for col=lane (4 FFMA chains) ----
        float h0 = 0.f, h1 = 0.f, h2 = 0.f, h3 = 0.f;
        #pragma unroll 4
        for (int k = 0; k < IN_DIM; k += 4) {
            float4 wv = *(const float4*)(wrow + k);
            float4 a0 = *(const float4*)(xw + 0 * NPAD + k);
            float4 a1 = *(const float4*)(xw + 1 * NPAD + k);
            float4 a2 = *(const float4*)(xw + 2 * NPAD + k);
            float4 a3 = *(const float4*)(xw + 3 * NPAD + k);
            h0 = fmaf(a0.x, wv.x, h0); h0 = fmaf(a0.y, wv.y, h0); h0 = fmaf(a0.z, wv.z, h0); h0 = fmaf(a0.w, wv.w, h0);
            h1 = fmaf(a1.x, wv.x, h1); h1 = fmaf(a1.y, wv.y, h1); h1 = fmaf(a1.z, wv.z, h1); h1 = fmaf(a1.w, wv.w, h1);
            h2 = fmaf(a2.x, wv.x, h2); h2 = fmaf(a2.y, wv.y, h2); h2 = fmaf(a2.z, wv.z, h2); h2 = fmaf(a2.w, wv.w, h2);
            h3 = fmaf(a3.x, wv.x, h3); h3 = fmaf(a3.y, wv.y, h3); h3 = fmaf(a3.z, wv.z, h3); h3 = fmaf(a3.w, wv.w, h3);
        }
        h0 = lrelu(h0 + bj); h1 = lrelu(h1 + bj); h2 = lrelu(h2 + bj); h3 = lrelu(h3 + bj);
        out[(size_t)(rbase + 0) * 32 + lane] = h0;
        out[(size_t)(rbase + 1) * 32 + lane] = h1;
        out[(size_t)(rbase + 2) * 32 + lane] = h2;
        out[(size_t)(rbase + 3) * 32 + lane] = h3;

        // ---- mu + ch GEMMs (f32x2, col-pair weights) ----
        ull acp[RPW][8];
        float ac16[RPW];
        ull amu01 = 0ull, amu23 = 0ull;
        #pragma unroll
        for (int r = 0; r < RPW; r++) {
            ac16[r] = 0.f;
            #pragma unroll
            for (int cp = 0; cp < 8; cp++) acp[r][cp] = 0ull;
        }
        #pragma unroll 2
        for (int k = 0; k < LATENT; k++) {
            float hv0 = __shfl_sync(0xffffffffu, h0, k);
            float hv1 = __shfl_sync(0xffffffffu, h1, k);
            float hv2 = __shfl_sync(0xffffffffu, h2, k);
            float hv3 = __shfl_sync(0xffffffffu, h3, k);
            float wm = sm[OFF_WMU + k * 32 + lane];
            ull wmd  = pk2(wm, wm);
            amu01 = fma2(pk2(hv0, hv1), wmd, amu01);
            amu23 = fma2(pk2(hv2, hv3), wmd, amu23);
            ull hd0 = pk2(hv0, hv0), hd1 = pk2(hv1, hv1), hd2 = pk2(hv2, hv2), hd3 = pk2(hv3, hv3);
            const ull* w2 = (const ull*)(sm + OFF_WCH + k * NPAD) + lane;
            #pragma unroll
            for (int cp = 0; cp < 8; cp++) {
                ull w = w2[cp * 32];
                acp[0][cp] = fma2(hd0, w, acp[0][cp]);
                acp[1][cp] = fma2(hd1, w, acp[1][cp]);
                acp[2][cp] = fma2(hd2, w, acp[2][cp]);
                acp[3][cp] = fma2(hd3, w, acp[3][cp]);
            }
            float wc16 = sm[OFF_WCH + k * NPAD + 512 + lane];
            ac16[0] = fmaf(hv0, wc16, ac16[0]);
            ac16[1] = fmaf(hv1, wc16, ac16[1]);
            ac16[2] = fmaf(hv2, wc16, ac16[2]);
            ac16[3] = fmaf(hv3, wc16, ac16[3]);
        }
        out[MU_OFF + (size_t)(rbase + 0) * 32 + lane] = lrelu(lo2(amu01) + bm);
        out[MU_OFF + (size_t)(rbase + 1) * 32 + lane] = lrelu(hi2(amu01) + bm);
        out[MU_OFF + (size_t)(rbase + 2) * 32 + lane] = lrelu(lo2(amu23) + bm);
        out[MU_OFF + (size_t)(rbase + 3) * 32 + lane] = lrelu(hi2(amu23) + bm);

        __syncwarp();                       // enc reads of xw done -> safe to overwrite with L
        ull* Lp = (ull*)xw;                 // dense pair layout: row i at i*LDW, 32x34 u64

        // ---- two sequential passes: rows (0,1) then (2,3) ----
        #pragma unroll
        for (int p = 0; p < 2; p++) {
            // scatter elts -> L (u64 = 2 batch rows)
            #pragma unroll
            for (int c = 0; c < 17; c++) {
                int e = c * 32 + lane;
                if (c == 16 && e >= NTRI) continue;
                int i = (int)((sqrtf(8.f * (float)e + 1.f) - 1.f) * 0.5f);
                int t = i * (i + 1) >> 1;
                if (e < t)               { i--; t -= i + 1; }
                else if (e >= t + i + 1) { t += i + 1; i++; }
                int off = i * LDW + (e - t);
                float bc = sm[OFF_BCH + e];
                float v0, v1;
                if (c < 16) {
                    ull q0 = acp[2 * p][c >> 1], q1 = acp[2 * p + 1][c >> 1];
                    if (c & 1) { v0 = hi2(q0); v1 = hi2(q1); }
                    else       { v0 = lo2(q0); v1 = lo2(q1); }
                } else { v0 = ac16[2 * p]; v1 = ac16[2 * p + 1]; }
                Lp[off] = pk2(lrelu(v0 + bc), lrelu(v1 + bc));
            }
            if (p == 0 && lane < 16) {      // zero pad (i, i+1) for even i (x garbage otherwise)
                int i = 2 * lane;
                Lp[i * LDW + i + 1] = 0ull;
            }
            __syncwarp();
            {                                // diag transform (lane = L-row)
                int off = lane * LDW + lane;
                ull v = Lp[off];
                float d0 = lo2(v), d1 = hi2(v);
                float s0 = (d0 > 20.f) ? d0 : log1pf(expf(d0));
                float s1 = (d1 > 20.f) ? d1 : log1pf(expf(d1));
                s0 = fminf(fmaxf(s0, 0.001f), 100.f) + 0.01f;
                s1 = fminf(fmaxf(s1, 0.001f), 100.f) + 0.01f;
                Lp[off] = pk2(s0, s1);
            }
            __syncwarp();

            // cov = L L^T + 0.01 I ; lane = output column
            ull Lk2[32];
            {
                const int klo = lane * LDW;
                #pragma unroll
                for (int j = 0; j < 32; j++) {
                    ull v = Lp[klo + j];     // 2-way bank conflict max
                    Lk2[j] = (j <= lane) ? v : 0ull;
                }
            }
            float* oc0 = out + COV_OFF + (size_t)(rbase + 2 * p)     * 1024;
            float* oc1 = out + COV_OFF + (size_t)(rbase + 2 * p + 1) * 1024;
            #pragma unroll
            for (int i = 0; i < 32; i++) {
                const ull* Lr = Lp + i * LDW;
                const int E = (i + 2) & ~1;        // even count incl. pad
                ull a0 = 0ull, a1 = 0ull, a2 = 0ull, a3 = 0ull;
                #pragma unroll
                for (int m = 0; m + 4 <= E; m += 4) {
                    ulonglong2 u = *(const ulonglong2*)(Lr + m);
                    ulonglong2 v = *(const ulonglong2*)(Lr + m + 2);
                    a0 = fma2(Lk2[m],     u.x, a0);
                    a1 = fma2(Lk2[m + 1], u.y, a1);
                    a2 = fma2(Lk2[m + 2], v.x, a2);
                    a3 = fma2(Lk2[m + 3], v.y, a3);
                }
                if (E & 2) {
                    int m = E & ~3;
                    ulonglong2 u = *(const ulonglong2*)(Lr + m);
                    a0 = fma2(Lk2[m],     u.x, a0);
                    a1 = fma2(Lk2[m + 1], u.y, a1);
                }
                float c0 = (lo2(a0) + lo2(a1)) + (lo2(a2) + lo2(a3));
                float c1 = (hi2(a0) + hi2(a1)) + (hi2(a2) + hi2(a3));
                if (lane == i) { c0 += 0.01f; c1 += 0.01f; }
                oc0[i * 32 + lane] = c0;
                oc1[i * 32 + lane] = c1;
            }
            __syncwarp();                    // cov reads done before next scatter / next tile x load
        }
    }
}

extern "C" void kernel_launch(void* const* d_in, const int* in_sizes, int n_in,
                              void* d_out, int out_size)
{
    (void)in_sizes; (void)n_in; (void)out_size;
    const float* x        = (const float*)d_in[0];
    const float* W_enc    = (const float*)d_in[1];
    const float* b_enc    = (const float*)d_in[2];
    const float* bn_gamma = (const float*)d_in[3];
    const float* bn_beta  = (const float*)d_in[4];
    const float* bn_mean  = (const float*)d_in[5];
    const float* bn_var   = (const float*)d_in[6];
    const float* W_mu     = (const float*)d_in[7];
    const float* b_mu     = (const float*)d_in[8];
    const float* W_ch     = (const float*)d_in[9];
    const float* b_ch     = (const float*)d_in[10];
    float* out = (float*)d_out;

    cudaFuncSetAttribute(pm_kernel, cudaFuncAttributeMaxDynamicSharedMemorySize,
                         SMEM_FLOATS * (int)sizeof(float));
    pm_kernel<<<GRID, THREADS, SMEM_FLOATS * sizeof(float)>>>(
        x, W_enc, b_enc, bn_gamma, bn_beta, bn_mean, bn_var,
        W_mu, b_mu, W_ch, b_ch, out);
}

// round 8
// speedup vs baseline: 1.4104x; 1.2558x over previous
#include <cuda_runtime.h>
#include <math.h>
#include <stdint.h>

#define BATCH   65536
#define IN_DIM  512
#define LATENT  32
#define NTRI    528
#define NPAD    544            // W_ch padded row (floats)
#define WENC_PAD 524           // conflict-free float4 weight rows
#define THREADS 512
#define WARPS   16
#define RPW     4
#define TILE_ROWS (WARPS*RPW)  // 64
#define NTILES  (BATCH/TILE_ROWS) // 1024
#define GRID    152

#define XH      272            // per-row stride (floats) of half-K x stage (256 + 16 pad)
#define WBUF_FLOATS 1088       // per-warp buffer: 4x272 x-halves OR one packed-tri L row (528)

// ---- smem layout (floats) ----
#define OFF_WENC 0
#define SZ_WENC  (LATENT*WENC_PAD)              // 16768
#define OFF_WCH  (OFF_WENC + SZ_WENC)           // 16768
#define SZ_WCH   (LATENT*NPAD)                  // 17408
#define OFF_WMU  (OFF_WCH + SZ_WCH)             // 34176
#define OFF_BENC (OFF_WMU + LATENT*LATENT)      // 35200
#define OFF_BMU  (OFF_BENC + 32)                // 35232
#define OFF_BCH  (OFF_BMU + 32)                 // 35264 (544)
#define OFF_S    (OFF_BCH + NPAD)               // 35808
#define OFF_WBUF (OFF_S + 32)                   // 35840 (16B aligned)
#define SMEM_FLOATS (OFF_WBUF + WARPS*WBUF_FLOATS) // 53248 floats = 212992 B

#define MU_OFF  ((size_t)BATCH*LATENT)
#define COV_OFF ((size_t)BATCH*LATENT*2)

__device__ __forceinline__ float lrelu(float v) { return v >= 0.f ? v : 0.01f * v; }

__global__ void __launch_bounds__(THREADS)
pm_kernel(const float* __restrict__ x,       const float* __restrict__ W_enc,
          const float* __restrict__ b_enc,   const float* __restrict__ bn_gamma,
          const float* __restrict__ bn_beta, const float* __restrict__ bn_mean,
          const float* __restrict__ bn_var,  const float* __restrict__ W_mu,
          const float* __restrict__ b_mu,    const float* __restrict__ W_ch,
          const float* __restrict__ b_ch,    float* __restrict__ out)
{
    extern __shared__ float sm[];
    const int tid = threadIdx.x;

    // ---- stage + fold weights into smem ----
    if (tid < 32) {
        float s = bn_gamma[tid] * rsqrtf(bn_var[tid] + 1e-5f);
        sm[OFF_S + tid]    = s;
        sm[OFF_BENC + tid] = (b_enc[tid] - bn_mean[tid]) * s + bn_beta[tid];
        sm[OFF_BMU + tid]  = b_mu[tid];
    }
    __syncthreads();
    for (int idx = tid; idx < IN_DIM * LATENT; idx += THREADS) {
        int k = idx >> 5, j = idx & 31;
        sm[OFF_WENC + j * WENC_PAD + k] = W_enc[idx] * sm[OFF_S + j];  // transposed + BN fold
    }
    for (int idx = tid; idx < LATENT * NPAD; idx += THREADS) {
        int k = idx / NPAD, c = idx - k * NPAD;
        sm[OFF_WCH + idx] = (c < NTRI) ? W_ch[k * NTRI + c] : 0.f;
    }
    for (int idx = tid; idx < LATENT * LATENT; idx += THREADS) sm[OFF_WMU + idx] = W_mu[idx];
    for (int idx = tid; idx < NPAD; idx += THREADS) sm[OFF_BCH + idx] = (idx < NTRI) ? b_ch[idx] : 0.f;
    __syncthreads();

    const int warp = tid >> 5, lane = tid & 31;
    float* xw = sm + OFF_WBUF + warp * WBUF_FLOATS;   // x half-tile stage / per-row L buffer
    const float* wrow = sm + OFF_WENC + lane * WENC_PAD;
    const float bj = sm[OFF_BENC + lane];
    const float bm = sm[OFF_BMU + lane];
    const int dio = ((lane * (lane + 1)) >> 1) + lane;   // diag offset of L-row 'lane'
    const int kbase = (lane * (lane + 1)) >> 1;          // gather base (mod-32 permutation)

    for (int tile = blockIdx.x; tile < NTILES; tile += gridDim.x) {
        const int rbase = tile * TILE_ROWS + warp * RPW;

        // ---- enc GEMM in two half-K passes ----
        float h0 = 0.f, h1 = 0.f, h2 = 0.f, h3 = 0.f;
        #pragma unroll
        for (int half = 0; half < 2; half++) {
            // stage x[4][256] (coalesced float4)
            #pragma unroll
            for (int r = 0; r < RPW; r++) {
                const float4* xg = (const float4*)(x + (size_t)(rbase + r) * IN_DIM + half * 256);
                #pragma unroll
                for (int c = 0; c < 2; c++) {
                    float4 v = xg[c * 32 + lane];
                    *(float4*)(xw + r * XH + c * 128 + lane * 4) = v;
                }
            }
            __syncwarp();
            const float* wh = wrow + half * 256;
            #pragma unroll 4
            for (int k = 0; k < 256; k += 4) {
                float4 wv = *(const float4*)(wh + k);
                float4 a0 = *(const float4*)(xw + 0 * XH + k);
                float4 a1 = *(const float4*)(xw + 1 * XH + k);
                float4 a2 = *(const float4*)(xw + 2 * XH + k);
                float4 a3 = *(const float4*)(xw + 3 * XH + k);
                h0 = fmaf(a0.x, wv.x, h0); h0 = fmaf(a0.y, wv.y, h0); h0 = fmaf(a0.z, wv.z, h0); h0 = fmaf(a0.w, wv.w, h0);
                h1 = fmaf(a1.x, wv.x, h1); h1 = fmaf(a1.y, wv.y, h1); h1 = fmaf(a1.z, wv.z, h1); h1 = fmaf(a1.w, wv.w, h1);
                h2 = fmaf(a2.x, wv.x, h2); h2 = fmaf(a2.y, wv.y, h2); h2 = fmaf(a2.z, wv.z, h2); h2 = fmaf(a2.w, wv.w, h2);
                h3 = fmaf(a3.x, wv.x, h3); h3 = fmaf(a3.y, wv.y, h3); h3 = fmaf(a3.z, wv.z, h3); h3 = fmaf(a3.w, wv.w, h3);
            }
            __syncwarp();   // done reading this half before restaging / L reuse
        }
        h0 = lrelu(h0 + bj); h1 = lrelu(h1 + bj); h2 = lrelu(h2 + bj); h3 = lrelu(h3 + bj);
        out[(size_t)(rbase + 0) * 32 + lane] = h0;
        out[(size_t)(rbase + 1) * 32 + lane] = h1;
        out[(size_t)(rbase + 2) * 32 + lane] = h2;
        out[(size_t)(rbase + 3) * 32 + lane] = h3;

        // ---- mu + ch GEMMs (scalar, round-1 proven) ----
        float amu0 = 0.f, amu1 = 0.f, amu2 = 0.f, amu3 = 0.f;
        float ac[RPW][17];
        #pragma unroll
        for (int r = 0; r < RPW; r++)
            #pragma unroll
            for (int c = 0; c < 17; c++) ac[r][c] = 0.f;

        #pragma unroll 2
        for (int k = 0; k < LATENT; k++) {
            float hv0 = __shfl_sync(0xffffffffu, h0, k);
            float hv1 = __shfl_sync(0xffffffffu, h1, k);
            float hv2 = __shfl_sync(0xffffffffu, h2, k);
            float hv3 = __shfl_sync(0xffffffffu, h3, k);
            float wm = sm[OFF_WMU + k * 32 + lane];
            amu0 = fmaf(hv0, wm, amu0); amu1 = fmaf(hv1, wm, amu1);
            amu2 = fmaf(hv2, wm, amu2); amu3 = fmaf(hv3, wm, amu3);
            const float* wck = sm + OFF_WCH + k * NPAD + lane;
            #pragma unroll
            for (int c = 0; c < 17; c++) {
                float wc = wck[c * 32];
                ac[0][c] = fmaf(hv0, wc, ac[0][c]);
                ac[1][c] = fmaf(hv1, wc, ac[1][c]);
                ac[2][c] = fmaf(hv2, wc, ac[2][c]);
                ac[3][c] = fmaf(hv3, wc, ac[3][c]);
            }
        }
        out[MU_OFF + (size_t)(rbase + 0) * 32 + lane] = lrelu(amu0 + bm);
        out[MU_OFF + (size_t)(rbase + 1) * 32 + lane] = lrelu(amu1 + bm);
        out[MU_OFF + (size_t)(rbase + 2) * 32 + lane] = lrelu(amu2 + bm);
        out[MU_OFF + (size_t)(rbase + 3) * 32 + lane] = lrelu(amu3 + bm);
        __syncwarp();

        // ---- cov: one batch row at a time through the shared 1088-float buffer ----
        float* Lb = xw;   // packed-tri L row buffer (528 floats used)
        #pragma unroll
        for (int r = 0; r < RPW; r++) {
            // scatter elts (offset == element index)
            #pragma unroll
            for (int c = 0; c < 17; c++) {
                int e = c * 32 + lane;
                if (c == 16 && e >= NTRI) continue;
                Lb[e] = lrelu(ac[r][c] + sm[OFF_BCH + e]);
            }
            __syncwarp();
            // diag transform (lane = L-row)
            {
                float d = Lb[dio];
                float sp = (d > 20.f) ? d : log1pf(expf(d));
                Lb[dio] = fminf(fmaxf(sp, 0.001f), 100.f) + 0.01f;
            }
            __syncwarp();
            // gather own row (conflict-free: tri(lane) mod 32 is a permutation)
            float Lk[32];
            #pragma unroll
            for (int j = 0; j < 32; j++) {
                float v = Lb[kbase + j];
                Lk[j] = (j <= lane) ? v : 0.f;
            }
            // compute & store
            float* oc = out + COV_OFF + (size_t)(rbase + r) * 1024;
            #pragma unroll
            for (int i = 0; i < 32; i++) {
                float a0 = 0.f, a1 = 0.f, a2 = 0.f, a3 = 0.f;
                #pragma unroll
                for (int j = 0; j <= i; j++) {
                    float lv = Lb[(i * (i + 1)) / 2 + j];   // consecutive -> vectorized broadcast
                    if      ((j & 3) == 0) a0 = fmaf(Lk[j], lv, a0);
                    else if ((j & 3) == 1) a1 = fmaf(Lk[j], lv, a1);
                    else if ((j & 3) == 2) a2 = fmaf(Lk[j], lv, a2);
                    else                   a3 = fmaf(Lk[j], lv, a3);
                }
                float cv = (a0 + a1) + (a2 + a3);
                if (lane == i) cv += 0.01f;
                oc[i * 32 + lane] = cv;
            }
            __syncwarp();   // reads done before next row's scatter / next tile x stage
        }
    }
}

extern "C" void kernel_launch(void* const* d_in, const int* in_sizes, int n_in,
                              void* d_out, int out_size)
{
    (void)in_sizes; (void)n_in; (void)out_size;
    const float* x        = (const float*)d_in[0];
    const float* W_enc    = (const float*)d_in[1];
    const float* b_enc    = (const float*)d_in[2];
    const float* bn_gamma = (const float*)d_in[3];
    const float* bn_beta  = (const float*)d_in[4];
    const float* bn_mean  = (const float*)d_in[5];
    const float* bn_var   = (const float*)d_in[6];
    const float* W_mu     = (const float*)d_in[7];
    const float* b_mu     = (const float*)d_in[8];
    const float* W_ch     = (const float*)d_in[9];
    const float* b_ch     = (const float*)d_in[10];
    float* out = (float*)d_out;

    cudaFuncSetAttribute(pm_kernel, cudaFuncAttributeMaxDynamicSharedMemorySize,
                         SMEM_FLOATS * (int)sizeof(float));
    pm_kernel<<<GRID, THREADS, SMEM_FLOATS * sizeof(float)>>>(
        x, W_enc, b_enc, bn_gamma, bn_beta, bn_mean, bn_var,
        W_mu, b_mu, W_ch, b_ch, out);
}